// round 11
// baseline (speedup 1.0000x reference)
#include <cuda_runtime.h>

// Problem constants
#define K_COLORS 512
#define NGRP     (K_COLORS / 4)       // 128 groups of 4 colors
#define HW       65536                // 256*256
#define B        8
#define PPT      2                    // pixels (batch images) per thread
#define NTHREADS 128
#define NBLOCKS  2048                 // 262144 threads = HW * (B/PPT)
#define NPIX     (HW * B)             // 524288
#define NOUT     (NPIX * 3)           // 1572864

// One group = 4 consecutive colors, coefficients pre-paired for f32x2 math:
// a0 = {(-2t0_k,-2t0_k+1),(-2t0_k+2,-2t0_k+3)}, likewise a1/a2/nn.
struct Grp { ulonglong2 a0, a1, a2, nn; };

__constant__ Grp    cG[NGRP];         // main-loop palette (const port, no L1tex)
__device__   Grp    gG[NGRP];         // staging, written by prep_kernel
__device__   float4 gC4[K_COLORS];    // AoS (-2t0,-2t1,-2t2,n) for the rescan

__device__ float        g_partials[NBLOCKS];
__device__ unsigned int g_count = 0;

// ---- packed f32x2 helpers ----
__device__ __forceinline__ unsigned long long fma2(unsigned long long a,
                                                   unsigned long long b,
                                                   unsigned long long c) {
    unsigned long long d;
    asm("fma.rn.f32x2 %0, %1, %2, %3;" : "=l"(d) : "l"(a), "l"(b), "l"(c));
    return d;
}
__device__ __forceinline__ unsigned long long bc2(float x) {
    unsigned int u = __float_as_uint(x);
    return ((unsigned long long)u << 32) | u;
}
__device__ __forceinline__ float lo_f(unsigned long long v) {
    return __uint_as_float((unsigned int)v);
}
__device__ __forceinline__ float hi_f(unsigned long long v) {
    return __uint_as_float((unsigned int)(v >> 32));
}

__global__ void __launch_bounds__(K_COLORS) prep_kernel(
    const float* __restrict__ table)
{
    const int k = threadIdx.x;
    float t0 = table[3 * k + 0];
    float t1 = table[3 * k + 1];
    float t2 = table[3 * k + 2];
    float n  = __fadd_rn(__fadd_rn(__fmul_rn(t0, t0), __fmul_rn(t1, t1)),
                         __fmul_rn(t2, t2));
    float a0 = -2.0f * t0, a1 = -2.0f * t1, a2 = -2.0f * t2;
    const int g4 = k >> 2, lane = k & 3;
    float* base = (float*)&gG[g4];
    base[0 * 4 + lane] = a0;
    base[1 * 4 + lane] = a1;
    base[2 * 4 + lane] = a2;
    base[3 * 4 + lane] = n;
    gC4[k] = make_float4(a0, a1, a2, n);
}

// Fused VQ + straight-through output + loss.
//
// ROUND-11 CHANGE vs round 9 (best, 53.7us, issue-bound at 52.6% with only
// 6.9 warps/SMSP): pixel-dimension subdivision ONLY. PPT 4->2 with 2x the
// threads doubles resident warps (12/SMSP under __launch_bounds__(128,12))
// with zero duplicated work and no merge step — unlike the failed round-10
// k-split, total issues are unchanged; the extra warps just cover the
// LDC -> FFMA2 -> FMNMX -> FSETP(13cy) -> SEL latency chains.
//
// Main loop per 4-color group per pixel: 6 FFMA2, 3-FMNMX reduce, strict-'<'
// commit of (min, group) in ascending group order. Exact index recovery:
// rescan the winning 4-color group with the bit-identical scalar FMA chain
// (f32x2 halves are IEEE-identical to fma.rn.f32); first '==' match is the
// argmin (jnp.argmin first-index semantics). Bit-validated rounds 4/6-10.
__global__ void __launch_bounds__(NTHREADS, 12) vq_kernel(
    const float* __restrict__ z,
    float* __restrict__ out,
    int out_size)
{
    __shared__ float sred[NTHREADS];
    __shared__ int   s_last;

    const int tid  = threadIdx.x;
    const int g    = blockIdx.x * NTHREADS + tid;   // 0..262143
    const int hw   = g & (HW - 1);
    const int bat0 = (g >> 16) * PPT;               // first batch image

    // Pixel components broadcast into both packed halves (loop-invariant).
    unsigned long long Xb[PPT], Yb[PPT], Zb[PPT];
#pragma unroll
    for (int p = 0; p < PPT; ++p) {
        const int base = (bat0 + p) * 3 * HW + hw;
        Xb[p] = bc2(z[base]);
        Yb[p] = bc2(z[base + HW]);
        Zb[p] = bc2(z[base + 2 * HW]);
    }

    float gbest[PPT];
    int   ggrp[PPT];
#pragma unroll
    for (int p = 0; p < PPT; ++p) { gbest[p] = 3.402823466e38f; ggrp[p] = 0; }

#pragma unroll 8
    for (int g4 = 0; g4 < NGRP; ++g4) {
        const Grp gr = cG[g4];                     // uniform -> const port
#pragma unroll
        for (int p = 0; p < PPT; ++p) {
            // d = x*(-2t0) + (y*(-2t1) + (z*(-2t2) + n)) — same chain
            // order/rounding as the reference scalar fmaf chain.
            unsigned long long d01 =
                fma2(Xb[p], gr.a0.x,
                     fma2(Yb[p], gr.a1.x, fma2(Zb[p], gr.a2.x, gr.nn.x)));
            unsigned long long d23 =
                fma2(Xb[p], gr.a0.y,
                     fma2(Yb[p], gr.a1.y, fma2(Zb[p], gr.a2.y, gr.nn.y)));
            float m = fminf(fminf(lo_f(d01), hi_f(d01)),
                            fminf(lo_f(d23), hi_f(d23)));
            bool lt  = m < gbest[p];               // earliest group on ties
            gbest[p] = fminf(gbest[p], m);
            ggrp[p]  = lt ? g4 : ggrp[p];
        }
    }

    // Exact index recovery (first '==' match inside the winning 4-color
    // group), fused with the STE epilogue + loss accumulation.
    float lsum = 0.0f;
#pragma unroll
    for (int p = 0; p < PPT; ++p) {
        const int   kb = ggrp[p] << 2;
        const float px = lo_f(Xb[p]);
        const float py = lo_f(Yb[p]);
        const float pz = lo_f(Zb[p]);
        int found = 1023;
#pragma unroll
        for (int i = 0; i < 4; ++i) {
            const float4 cc = __ldg(&gC4[kb + i]);
            float d = fmaf(px, cc.x, fmaf(py, cc.y, fmaf(pz, cc.z, cc.w)));
            int kc = (d == gbest[p]) ? (kb + i) : 1023;
            found  = min(found, kc);
        }
        const float4 cc = __ldg(&gC4[found]);
        float q0 = -0.5f * cc.x;                 // exact recovery of t from -2t
        float q1 = -0.5f * cc.y;
        float q2 = -0.5f * cc.z;
        float d0 = __fsub_rn(q0, px);
        float d1 = __fsub_rn(q1, py);
        float d2 = __fsub_rn(q2, pz);
        const int base = (bat0 + p) * 3 * HW + hw;
        out[base]          = __fadd_rn(px, d0);  // zl + (z_q - zl)
        out[base + HW]     = __fadd_rn(py, d1);
        out[base + 2 * HW] = __fadd_rn(pz, d2);
        lsum = fmaf(d0, d0, lsum);
        lsum = fmaf(d1, d1, lsum);
        lsum = fmaf(d2, d2, lsum);
    }

    // Deterministic block reduction.
    sred[tid] = lsum;
    __syncthreads();
#pragma unroll
    for (int s = NTHREADS / 2; s > 0; s >>= 1) {
        if (tid < s) sred[tid] += sred[tid + s];
        __syncthreads();
    }

    // Last-block-done final reduction (single fused kernel).
    if (tid == 0) {
        g_partials[blockIdx.x] = sred[0];
        __threadfence();
        unsigned int prev = atomicAdd(&g_count, 1u);
        s_last = (prev == NBLOCKS - 1) ? 1 : 0;
    }
    __syncthreads();

    if (s_last) {
        __threadfence();
        volatile float* vp = g_partials;
        float acc = 0.0f;
        for (int i = tid; i < NBLOCKS; i += NTHREADS) acc += vp[i];
        sred[tid] = acc;
        __syncthreads();
#pragma unroll
        for (int s = NTHREADS / 2; s > 0; s >>= 1) {
            if (tid < s) sred[tid] += sred[tid + s];
            __syncthreads();
        }
        if (tid == 0) {
            float m    = sred[0] / (float)NOUT;
            float loss = __fadd_rn(10.0f * m, m);
            for (int i = NOUT; i < out_size; ++i) out[i] = loss;
            g_count = 0;   // reset for the next graph replay
        }
    }
}

extern "C" void kernel_launch(void* const* d_in, const int* in_sizes, int n_in,
                              void* d_out, int out_size)
{
    const float* z     = (const float*)d_in[0];
    const float* table = (const float*)d_in[1];
    float* out         = (float*)d_out;

    prep_kernel<<<1, K_COLORS>>>(table);

    // Stage -> constant bank, device-to-device async (graph-capturable).
    void* gG_addr = nullptr;
    cudaGetSymbolAddress(&gG_addr, gG);
    cudaMemcpyToSymbolAsync(cG, gG_addr, sizeof(gG), 0,
                            cudaMemcpyDeviceToDevice, 0);

    vq_kernel<<<NBLOCKS, NTHREADS>>>(z, out, out_size);
}

// round 12
// speedup vs baseline: 1.8058x; 1.8058x over previous
#include <cuda_runtime.h>

// Problem constants
#define K_COLORS 512
#define NGRP     (K_COLORS / 4)       // 128 groups of 4 colors
#define NCONST   40                   // groups 0..39 via constant port (LDC)
#define NSMEM    (NGRP - NCONST)      // groups 40..127 via shared mem (LDS)
#define HW       65536                // 256*256
#define B        8
#define PPT      4                    // pixels (batch images) per thread
#define NTHREADS 128
#define NBLOCKS  1024                 // 131072 threads = HW * (B/PPT)
#define NPIX     (HW * B)             // 524288
#define NOUT     (NPIX * 3)           // 1572864

// One group = 4 consecutive colors, coefficients pre-paired for f32x2 math:
// a0 = {(-2t0_k,-2t0_k+1),(-2t0_k+2,-2t0_k+3)}, likewise a1/a2/nn.
struct Grp { ulonglong2 a0, a1, a2, nn; };

__constant__ Grp    cG[NGRP];         // full palette in const bank
__device__   Grp    gG[NGRP];         // staging, written by prep_kernel
__device__   float4 gC4[K_COLORS];    // AoS (-2t0,-2t1,-2t2,n) for the rescan

__device__ float        g_partials[NBLOCKS];
__device__ unsigned int g_count = 0;

// ---- packed f32x2 helpers ----
__device__ __forceinline__ unsigned long long fma2(unsigned long long a,
                                                   unsigned long long b,
                                                   unsigned long long c) {
    unsigned long long d;
    asm("fma.rn.f32x2 %0, %1, %2, %3;" : "=l"(d) : "l"(a), "l"(b), "l"(c));
    return d;
}
__device__ __forceinline__ unsigned long long bc2(float x) {
    unsigned int u = __float_as_uint(x);
    return ((unsigned long long)u << 32) | u;
}
__device__ __forceinline__ float lo_f(unsigned long long v) {
    return __uint_as_float((unsigned int)v);
}
__device__ __forceinline__ float hi_f(unsigned long long v) {
    return __uint_as_float((unsigned int)(v >> 32));
}

__global__ void __launch_bounds__(K_COLORS) prep_kernel(
    const float* __restrict__ table)
{
    const int k = threadIdx.x;
    float t0 = table[3 * k + 0];
    float t1 = table[3 * k + 1];
    float t2 = table[3 * k + 2];
    float n  = __fadd_rn(__fadd_rn(__fmul_rn(t0, t0), __fmul_rn(t1, t1)),
                         __fmul_rn(t2, t2));
    float a0 = -2.0f * t0, a1 = -2.0f * t1, a2 = -2.0f * t2;
    const int g4 = k >> 2, lane = k & 3;
    float* base = (float*)&gG[g4];
    base[0 * 4 + lane] = a0;
    base[1 * 4 + lane] = a1;
    base[2 * 4 + lane] = a2;
    base[3 * 4 + lane] = n;
    gC4[k] = make_float4(a0, a1, a2, n);
}

// Fused VQ + straight-through output + loss.
//
// ROUND-12 MODEL (calibrated from rounds 9/11): every palette-fetch path
// serializes per-SM — LDC.128 ~7 cyc, broadcast LDS.128 ~4 cyc, uniform
// LDG.128 ~8.6 cyc each. Round 9 (all-const) was constant-port bound:
// runtime tracked LDC-count x ~7cyc exactly across rounds 9/11. Fix: SPLIT
// the 128-group sweep across two independent ports — groups 0..39 from the
// constant bank (LDC), groups 40..127 from shared memory (LDS) — so each
// port's serialized cost (~31k / ~39k cyc per SM) overlaps and both drop
// below the math issue budget.
//
// Tie semantics stay exact: both loops scan ascending group ids with a
// strict '<' commit, so the earliest group wins ties; the final 4-color
// rescan recomputes the bit-identical scalar FMA chain (f32x2 halves are
// IEEE-identical to fma.rn.f32) and the first '==' match is the argmin
// (jnp.argmin first-index semantics). Bit-validated rounds 4/6-11.
__global__ void __launch_bounds__(NTHREADS) vq_kernel(
    const float* __restrict__ z,
    float* __restrict__ out,
    int out_size)
{
    __shared__ Grp   sG[NSMEM];        // groups 40..127
    __shared__ float sred[NTHREADS];
    __shared__ int   s_last;

    const int tid  = threadIdx.x;

    // Cooperative copy of the smem palette slice (88 Grp = 352 x 16B).
    {
        const ulonglong2* src = (const ulonglong2*)&gG[NCONST];
        ulonglong2*       dst = (ulonglong2*)sG;
        for (int i = tid; i < NSMEM * 4; i += NTHREADS) dst[i] = src[i];
    }

    const int g    = blockIdx.x * NTHREADS + tid;   // 0..131071
    const int hw   = g & (HW - 1);
    const int bat0 = (g >> 16) * PPT;               // first batch image

    // Pixel components broadcast into both packed halves (loop-invariant).
    unsigned long long Xb[PPT], Yb[PPT], Zb[PPT];
#pragma unroll
    for (int p = 0; p < PPT; ++p) {
        const int base = (bat0 + p) * 3 * HW + hw;
        Xb[p] = bc2(z[base]);
        Yb[p] = bc2(z[base + HW]);
        Zb[p] = bc2(z[base + 2 * HW]);
    }

    float gbest[PPT];
    int   ggrp[PPT];
#pragma unroll
    for (int p = 0; p < PPT; ++p) { gbest[p] = 3.402823466e38f; ggrp[p] = 0; }

    __syncthreads();   // smem palette ready

    // ---- Loop 1: groups 0..39 via the constant port ----
#pragma unroll 8
    for (int g4 = 0; g4 < NCONST; ++g4) {
        const Grp gr = cG[g4];                     // uniform -> const port
#pragma unroll
        for (int p = 0; p < PPT; ++p) {
            unsigned long long d01 =
                fma2(Xb[p], gr.a0.x,
                     fma2(Yb[p], gr.a1.x, fma2(Zb[p], gr.a2.x, gr.nn.x)));
            unsigned long long d23 =
                fma2(Xb[p], gr.a0.y,
                     fma2(Yb[p], gr.a1.y, fma2(Zb[p], gr.a2.y, gr.nn.y)));
            float m = fminf(fminf(lo_f(d01), hi_f(d01)),
                            fminf(lo_f(d23), hi_f(d23)));
            bool lt  = m < gbest[p];               // earliest group on ties
            gbest[p] = fminf(gbest[p], m);
            ggrp[p]  = lt ? g4 : ggrp[p];
        }
    }

    // ---- Loop 2: groups 40..127 via shared memory (broadcast LDS) ----
#pragma unroll 8
    for (int q = 0; q < NSMEM; ++q) {
        const int g4 = NCONST + q;
        const Grp gr = sG[q];                      // broadcast LDS.128 x4
#pragma unroll
        for (int p = 0; p < PPT; ++p) {
            unsigned long long d01 =
                fma2(Xb[p], gr.a0.x,
                     fma2(Yb[p], gr.a1.x, fma2(Zb[p], gr.a2.x, gr.nn.x)));
            unsigned long long d23 =
                fma2(Xb[p], gr.a0.y,
                     fma2(Yb[p], gr.a1.y, fma2(Zb[p], gr.a2.y, gr.nn.y)));
            float m = fminf(fminf(lo_f(d01), hi_f(d01)),
                            fminf(lo_f(d23), hi_f(d23)));
            bool lt  = m < gbest[p];               // strictly larger ids: only
            gbest[p] = fminf(gbest[p], m);         // replace on strictly less
            ggrp[p]  = lt ? g4 : ggrp[p];
        }
    }

    // Exact index recovery (first '==' match inside the winning 4-color
    // group), fused with the STE epilogue + loss accumulation.
    float lsum = 0.0f;
#pragma unroll
    for (int p = 0; p < PPT; ++p) {
        const int   kb = ggrp[p] << 2;
        const float px = lo_f(Xb[p]);
        const float py = lo_f(Yb[p]);
        const float pz = lo_f(Zb[p]);
        int found = 1023;
#pragma unroll
        for (int i = 0; i < 4; ++i) {
            const float4 cc = __ldg(&gC4[kb + i]);
            float d = fmaf(px, cc.x, fmaf(py, cc.y, fmaf(pz, cc.z, cc.w)));
            int kc = (d == gbest[p]) ? (kb + i) : 1023;
            found  = min(found, kc);
        }
        const float4 cc = __ldg(&gC4[found]);
        float q0 = -0.5f * cc.x;                 // exact recovery of t from -2t
        float q1 = -0.5f * cc.y;
        float q2 = -0.5f * cc.z;
        float d0 = __fsub_rn(q0, px);
        float d1 = __fsub_rn(q1, py);
        float d2 = __fsub_rn(q2, pz);
        const int base = (bat0 + p) * 3 * HW + hw;
        out[base]          = __fadd_rn(px, d0);  // zl + (z_q - zl)
        out[base + HW]     = __fadd_rn(py, d1);
        out[base + 2 * HW] = __fadd_rn(pz, d2);
        lsum = fmaf(d0, d0, lsum);
        lsum = fmaf(d1, d1, lsum);
        lsum = fmaf(d2, d2, lsum);
    }

    // Deterministic block reduction.
    sred[tid] = lsum;
    __syncthreads();
#pragma unroll
    for (int s = NTHREADS / 2; s > 0; s >>= 1) {
        if (tid < s) sred[tid] += sred[tid + s];
        __syncthreads();
    }

    // Last-block-done final reduction (single fused kernel).
    if (tid == 0) {
        g_partials[blockIdx.x] = sred[0];
        __threadfence();
        unsigned int prev = atomicAdd(&g_count, 1u);
        s_last = (prev == NBLOCKS - 1) ? 1 : 0;
    }
    __syncthreads();

    if (s_last) {
        __threadfence();
        volatile float* vp = g_partials;
        float acc = 0.0f;
        for (int i = tid; i < NBLOCKS; i += NTHREADS) acc += vp[i];
        sred[tid] = acc;
        __syncthreads();
#pragma unroll
        for (int s = NTHREADS / 2; s > 0; s >>= 1) {
            if (tid < s) sred[tid] += sred[tid + s];
            __syncthreads();
        }
        if (tid == 0) {
            float m    = sred[0] / (float)NOUT;
            float loss = __fadd_rn(10.0f * m, m);
            for (int i = NOUT; i < out_size; ++i) out[i] = loss;
            g_count = 0;   // reset for the next graph replay
        }
    }
}

extern "C" void kernel_launch(void* const* d_in, const int* in_sizes, int n_in,
                              void* d_out, int out_size)
{
    const float* z     = (const float*)d_in[0];
    const float* table = (const float*)d_in[1];
    float* out         = (float*)d_out;

    prep_kernel<<<1, K_COLORS>>>(table);

    // Stage -> constant bank, device-to-device async (graph-capturable).
    void* gG_addr = nullptr;
    cudaGetSymbolAddress(&gG_addr, gG);
    cudaMemcpyToSymbolAsync(cG, gG_addr, sizeof(gG), 0,
                            cudaMemcpyDeviceToDevice, 0);

    vq_kernel<<<NBLOCKS, NTHREADS>>>(z, out, out_size);
}